// round 5
// baseline (speedup 1.0000x reference)
#include <cuda_runtime.h>
#include <cuda_bf16.h>
#include <math.h>

// Fixed shapes
#define B_ 32
#define C_ 6
#define T_ 64
#define K_ 8
#define N_ 128
#define NSEG 1016
#define NSEGP 1024
#define NCL 2048
#define NCLP2 1024             // candidate pairs
#define EPS_ 1e-6f
#define THRESH_ 0.5f

#define THREADS 256
#define GW 4                   // warps per point-group
#define GL 128                 // lanes per point-group
#define NG 2                   // groups per block
#define M 4                    // points per group
#define PTS_BLK (NG * M)       // 8
#define NCHUNK (T_ / PTS_BLK)  // 8
// grid = B*C*NCHUNK = 1536

typedef unsigned long long u64;

__device__ __forceinline__ u64 F2ADD(u64 a, u64 b) {
    u64 d; asm("add.rn.f32x2 %0,%1,%2;" : "=l"(d) : "l"(a), "l"(b)); return d;
}
__device__ __forceinline__ u64 F2SUB(u64 a, u64 b) {
    u64 d; asm("sub.rn.f32x2 %0,%1,%2;" : "=l"(d) : "l"(a), "l"(b)); return d;
}
__device__ __forceinline__ u64 F2MUL(u64 a, u64 b) {
    u64 d; asm("mul.rn.f32x2 %0,%1,%2;" : "=l"(d) : "l"(a), "l"(b)); return d;
}
__device__ __forceinline__ u64 F2FMA(u64 a, u64 b, u64 c) {
    u64 d; asm("fma.rn.f32x2 %0,%1,%2,%3;" : "=l"(d) : "l"(a), "l"(b), "l"(c)); return d;
}
__device__ __forceinline__ u64 F2PK(float lo, float hi) {
    u64 d; asm("mov.b64 %0,{%1,%2};" : "=l"(d) : "f"(lo), "f"(hi)); return d;
}
__device__ __forceinline__ void F2UP(u64 a, float& lo, float& hi) {
    asm("mov.b64 {%0,%1},%2;" : "=f"(lo), "=f"(hi) : "l"(a));
}
__device__ __forceinline__ float frcp(float x) {
    float r; asm("rcp.approx.f32 %0,%1;" : "=f"(r) : "f"(x)); return r;
}

__global__ void offroad_init_kernel(float* out) {
    int i = threadIdx.x;
    if (i < B_ * C_) out[i] = 0.0f;
}

__global__ __launch_bounds__(THREADS, 4)
void offroad_kernel(const float* __restrict__ points,
                    const float* __restrict__ road_boundary,
                    const float* __restrict__ centerlines,
                    float* __restrict__ out) {
    __shared__ float4 sA[NSEGP];     // (-ax,-ax,-ay,-ay)
    __shared__ float4 sD[NSEGP];     // (-dx,-dx,-dy,-dy)
    __shared__ float4 sCl[NCLP2];    // (-qx0,-qx1,-qy0,-qy1) per cand pair
    __shared__ float2 sRedA[NG][GW][M];
    __shared__ float2 sRedB[NG][GW][M];
    __shared__ float  sTerm[PTS_BLK];

    const int bid = blockIdx.x;
    const int chunk = bid & 7;
    const int c = (bid >> 3) % C_;
    const int b = bid / (8 * C_);
    const int tid = threadIdx.x;

    // ---- fill segments ----
    {
        const float2* rb = (const float2*)road_boundary + (size_t)b * K_ * N_;
        #pragma unroll
        for (int s0 = 0; s0 < NSEGP; s0 += THREADS) {
            int s = s0 + tid;
            float nax, nay, ndx, ndy;
            if (s < NSEG) {
                int k = s / (N_ - 1);
                int j = s - k * (N_ - 1);
                float2 a = rb[k * N_ + j];
                float2 e = rb[k * N_ + j + 1];
                nax = -a.x; nay = -a.y;
                ndx = a.x - e.x; ndy = a.y - e.y;
            } else {
                nax = -1e19f; nay = -1e19f; ndx = 0.0f; ndy = 0.0f;
            }
            sA[s] = make_float4(nax, nax, nay, nay);
            sD[s] = make_float4(ndx, ndx, ndy, ndy);
        }
    }
    // ---- fill centerlines (negated, pair-SoA) ----
    {
        const float4* cl4 = (const float4*)(centerlines + (size_t)b * NCL * 2);
        #pragma unroll
        for (int p0 = 0; p0 < NCLP2; p0 += THREADS) {
            int pi = p0 + tid;
            float4 v = cl4[pi];     // (q0x,q0y,q1x,q1y)
            sCl[pi] = make_float4(-v.x, -v.z, -v.y, -v.w);
        }
    }
    __syncthreads();

    const int grp = tid >> 7;        // 0..1
    const int wig = (tid >> 5) & 3;  // warp in group
    const int lG  = tid & 127;       // lane in group

    float px[M], py[M];
    {
        const float2* pp = (const float2*)points +
            ((size_t)(b * C_ + c)) * T_ + chunk * PTS_BLK + grp * M;
        #pragma unroll
        for (int j = 0; j < M; j++) { float2 p = pp[j]; px[j] = p.x; py[j] = p.y; }
    }

    // ---- Phase A: argmin over candidates (packed over cand pairs) ----
    u64 pxd[M], pyd[M];
    #pragma unroll
    for (int j = 0; j < M; j++) { pxd[j] = F2PK(px[j], px[j]); pyd[j] = F2PK(py[j], py[j]); }

    float sc[M]; int bi[M];
    #pragma unroll
    for (int j = 0; j < M; j++) { sc[j] = 3.4e38f; bi[j] = 0; }

    #pragma unroll
    for (int it = 0; it < NCLP2 / GL; it++) {       // 8 iters
        int pi = lG + it * GL;
        float4 nq = sCl[pi];
        u64 nqx = F2PK(nq.x, nq.y);
        u64 nqy = F2PK(nq.z, nq.w);
        int c0 = 2 * pi;
        #pragma unroll
        for (int j = 0; j < M; j++) {
            u64 ax = F2ADD(pxd[j], nqx);            // px - qx (pair)
            u64 ay = F2ADD(pyd[j], nqy);
            u64 d2 = F2FMA(ay, ay, F2MUL(ax, ax));
            float d20, d21; F2UP(d2, d20, d21);
            float pmin = fminf(d20, d21);
            int   pidx = c0 + ((d21 < d20) ? 1 : 0);
            if (pmin < sc[j]) { sc[j] = pmin; bi[j] = pidx; }
        }
    }
    #pragma unroll
    for (int off = 16; off; off >>= 1) {
        #pragma unroll
        for (int j = 0; j < M; j++) {
            float os = __shfl_xor_sync(0xffffffffu, sc[j], off);
            int   oi = __shfl_xor_sync(0xffffffffu, bi[j], off);
            if (os < sc[j] || (os == sc[j] && oi < bi[j])) { sc[j] = os; bi[j] = oi; }
        }
    }
    if ((tid & 31) == 0) {
        #pragma unroll
        for (int j = 0; j < M; j++)
            sRedA[grp][wig][j] = make_float2(sc[j], __int_as_float(bi[j]));
    }
    __syncthreads();
    // combine 4 warps (all threads, broadcast reads)
    #pragma unroll
    for (int j = 0; j < M; j++) {
        float bs = 3.4e38f; int bb = 0x7fffffff;
        #pragma unroll
        for (int w4 = 0; w4 < GW; w4++) {
            float2 e = sRedA[grp][w4][j];
            int ei = __float_as_int(e.y);
            if (e.x < bs || (e.x == bs && ei < bb)) { bs = e.x; bb = ei; }
        }
        bi[j] = bb;
    }

    // per-pair packed constants
    float dax[M], day[M];
    const float* clf = (const float*)sCl;
    #pragma unroll
    for (int j = 0; j < M; j++) {
        int p_ = bi[j] >> 1, h_ = bi[j] & 1;
        float nqx = clf[p_ * 4 + h_];
        float nqy = clf[p_ * 4 + 2 + h_];
        dax[j] = -nqx - px[j];     // qx - px
        day[j] = -nqy - py[j];
    }
    u64 px2[2]   = { F2PK(px[0], px[1]),   F2PK(px[2], px[3]) };
    u64 py2[2]   = { F2PK(py[0], py[1]),   F2PK(py[2], py[3]) };
    u64 dax2[2]  = { F2PK(dax[0], dax[1]), F2PK(dax[2], dax[3]) };
    u64 nday2[2] = { F2PK(-day[0], -day[1]), F2PK(-day[2], -day[3]) };
    const u64 neps2 = F2PK(-EPS_, -EPS_);

    // ---- Phase B: fused distance + intersection over segments ----
    float mind2[M], hAcc[M];
    #pragma unroll
    for (int j = 0; j < M; j++) { mind2[j] = 3.4e38f; hAcc[j] = 3.4e38f; }

    #pragma unroll 4
    for (int it = 0; it < NSEGP / GL; it++) {       // 8 iters
        int s = lG + it * GL;
        float4 A = sA[s];
        float4 D = sD[s];
        u64 nax2 = F2PK(A.x, A.y), nay2 = F2PK(A.z, A.w);
        u64 ndx2 = F2PK(D.x, D.y), ndy2 = F2PK(D.z, D.w);
        float len2 = fmaf(D.x, D.x, fmaf(D.z, D.z, EPS_));
        float r = frcp(len2);
        u64 ninv2 = F2PK(-r, -r);
        #pragma unroll
        for (int q = 0; q < 2; q++) {
            int j0 = 2 * q, j1 = 2 * q + 1;
            u64 v1x = F2ADD(px2[q], nax2);          // p - a
            u64 v1y = F2ADD(py2[q], nay2);
            u64 ndt = F2FMA(v1y, ndy2, F2MUL(v1x, ndx2));   // -(v1.d)
            u64 pr  = F2MUL(ndt, ninv2);            // dot/(len2+eps)
            float p0, p1; F2UP(pr, p0, p1);
            p0 = __saturatef(p0); p1 = __saturatef(p1);
            pr = F2PK(p0, p1);
            u64 ex = F2FMA(ndx2, pr, v1x);          // v1x - dx*pr
            u64 ey = F2FMA(ndy2, pr, v1y);
            u64 d2 = F2FMA(ey, ey, F2MUL(ex, ex));
            float d20, d21; F2UP(d2, d20, d21);
            mind2[j0] = fminf(mind2[j0], d20);
            mind2[j1] = fminf(mind2[j1], d21);
            // nw = -(cross(da,db)+eps);  c1 = cross(da,v1);  c2 = cross(db,v1)
            u64 nw = F2FMA(nday2[q], ndx2, F2FMA(dax2[q], ndy2, neps2));
            u64 c1 = F2FMA(dax2[q], v1y, F2MUL(nday2[q], v1x));
            u64 c2 = F2SUB(F2MUL(ndy2, v1x), F2MUL(ndx2, v1y));
            u64 s1 = F2MUL(c1, F2ADD(c1, nw));      // c1*(c1-w)
            u64 s2 = F2MUL(c2, F2ADD(c2, nw));      // c2*(c2-w)
            float s10, s11, s20, s21;
            F2UP(s1, s10, s11); F2UP(s2, s20, s21);
            hAcc[j0] = fminf(hAcc[j0], fmaxf(s10, s20));   // hit iff <= 0
            hAcc[j1] = fminf(hAcc[j1], fmaxf(s11, s21));
        }
    }
    #pragma unroll
    for (int off = 16; off; off >>= 1) {
        #pragma unroll
        for (int j = 0; j < M; j++) {
            mind2[j] = fminf(mind2[j], __shfl_xor_sync(0xffffffffu, mind2[j], off));
            hAcc[j]  = fminf(hAcc[j],  __shfl_xor_sync(0xffffffffu, hAcc[j], off));
        }
    }
    if ((tid & 31) == 0) {
        #pragma unroll
        for (int j = 0; j < M; j++)
            sRedB[grp][wig][j] = make_float2(mind2[j], hAcc[j]);
    }
    __syncthreads();

    if (tid < PTS_BLK) {
        int g_ = tid >> 2, j_ = tid & 3;
        float md2 = 3.4e38f, ha = 3.4e38f;
        #pragma unroll
        for (int w4 = 0; w4 < GW; w4++) {
            float2 e = sRedB[g_][w4][j_];
            md2 = fminf(md2, e.x);
            ha  = fminf(ha, e.y);
        }
        float md = sqrtf(md2);
        md = (ha <= 0.0f) ? md : -md;      // intersection -> outside (+), else inside (-)
        sTerm[tid] = fmaxf(md + THRESH_, 0.0f);
    }
    __syncthreads();
    if (tid == 0) {
        float ssum = 0.0f;
        #pragma unroll
        for (int i = 0; i < PTS_BLK; i++) ssum += sTerm[i];
        atomicAdd(&out[b * C_ + c], ssum);
    }
}

extern "C" void kernel_launch(void* const* d_in, const int* in_sizes, int n_in,
                              void* d_out, int out_size) {
    const float* points      = (const float*)d_in[0];
    const float* road_bound  = (const float*)d_in[1];
    const float* centerlines = (const float*)d_in[2];
    float* out = (float*)d_out;
    (void)in_sizes; (void)n_in; (void)out_size;

    offroad_init_kernel<<<1, 256>>>(out);
    offroad_kernel<<<B_ * C_ * NCHUNK, THREADS>>>(points, road_bound, centerlines, out);
}